// round 2
// baseline (speedup 1.0000x reference)
#include <cuda_runtime.h>

#define B_TOT   8192
#define CAR     8
#define NAG     64
#define HID     256
#define ENC     257
#define QIN     265
#define ADIM    30
#define SROW    520
#define HPITCH  72      // floats; 288B row stride -> 16B aligned, modest STS conflicts only

// shared layout (in floats)
#define OFF_S   0
#define OFF_V   528
#define OFF_H   592                      // 592*4 = 2368, 16B aligned
#define OFF_X   (OFF_H + HID * HPITCH)   // 19024
#define OFF_Y   (OFF_X + 272)            // 19296
#define SMEM_FLOATS (OFF_Y + 256)        // 19552
#define SMEM_BYTES  (SMEM_FLOATS * 4)    // 78208 B

union F2U { unsigned long long u; float2 f; };

// d = a*b + d, packed 2xfp32 (sm_103a FFMA2, PTX-only)
__device__ __forceinline__ void fma2(unsigned long long& d,
                                     unsigned long long a,
                                     unsigned long long b) {
    asm("fma.rn.f32x2 %0, %1, %2, %0;" : "+l"(d) : "l"(a), "l"(b));
}

__global__ void __launch_bounds__(288, 2) qnet_kernel(
    const float* __restrict__ s,
    const float* __restrict__ W1, const float* __restrict__ b1,
    const float* __restrict__ W2, const float* __restrict__ b2,
    const float* __restrict__ Qw1, const float* __restrict__ Qb1,
    const float* __restrict__ Qw2, const float* __restrict__ Qb2,
    float* __restrict__ out)
{
    extern __shared__ float sm[];
    float* s_sh = sm + OFF_S;
    float* v_sh = sm + OFF_V;
    float* h_sh = sm + OFF_H;
    float* x_sh = sm + OFF_X;
    float* y_sh = sm + OFF_Y;

    const int tid = threadIdx.x;
    const int b   = blockIdx.x;

    // ---- Phase 0: stage s row ----
    const float* srow = s + (size_t)b * SROW;
    for (int i = tid; i < SROW; i += 288) s_sh[i] = srow[i];
    __syncthreads();

    // validity: exact fp32 compare against -1.0
    if (tid < NAG) {
        bool v = true;
        #pragma unroll
        for (int c = 0; c < CAR; c++)
            v = v && (s_sh[CAR + tid * CAR + c] != -1.0f);
        v_sh[tid] = v ? 1.0f : 0.0f;
    }

    // ---- Phase 1: h[k][n] = relu(surr[n] . W1[:,k] + b1[k]) (transposed store) ----
    if (tid < HID) {
        const int k = tid;
        float w1r[CAR];
        #pragma unroll
        for (int c = 0; c < CAR; c++) w1r[c] = W1[c * HID + k];
        const float bk = b1[k];
        #pragma unroll 4
        for (int n = 0; n < NAG; n++) {
            float a = bk;
            #pragma unroll
            for (int c = 0; c < CAR; c++)
                a = fmaf(s_sh[CAR + n * CAR + c], w1r[c], a);
            h_sh[k * HPITCH + n] = fmaxf(a, 0.0f);
        }
    }
    __syncthreads();

    // ---- Phase 2: per output column e, accumulate over k for all 64 agents ----
    // enc[n][e] = relu(sum_k h[n][k]*W2[k][e] + b2[e]); x[8+e] = sum_n valid[n]*enc[n][e]
    if (tid < ENC) {
        const int e = tid;
        const float be = b2[e];
        F2U acc[NAG / 2];
        F2U binit; binit.f = make_float2(be, be);
        #pragma unroll
        for (int j = 0; j < NAG / 2; j++) acc[j].u = binit.u;

        #pragma unroll 2
        for (int k = 0; k < HID; k++) {
            const float w = W2[k * ENC + e];       // coalesced, L2-resident
            F2U w2; w2.f = make_float2(w, w);
            const ulonglong2* hp =
                reinterpret_cast<const ulonglong2*>(h_sh + k * HPITCH);
            #pragma unroll
            for (int j = 0; j < 16; j++) {          // 16x LDS128 broadcast
                ulonglong2 hv = hp[j];
                fma2(acc[2 * j + 0].u, hv.x, w2.u);
                fma2(acc[2 * j + 1].u, hv.y, w2.u);
            }
        }

        float sum = 0.0f;
        #pragma unroll
        for (int j = 0; j < NAG / 2; j++) {
            float lo = fmaxf(acc[j].f.x, 0.0f);
            float hi = fmaxf(acc[j].f.y, 0.0f);
            sum += lo * v_sh[2 * j] + hi * v_sh[2 * j + 1];
        }
        x_sh[CAR + e] = sum;
    }
    if (tid < CAR) x_sh[tid] = s_sh[tid];
    __syncthreads();

    // ---- Phase 4: y = relu(x @ Qw1 + Qb1) ----
    if (tid < HID) {
        const int j = tid;
        float a = Qb1[j];
        #pragma unroll 5
        for (int i = 0; i < QIN; i++)
            a = fmaf(x_sh[i], Qw1[i * HID + j], a);
        y_sh[j] = fmaxf(a, 0.0f);
    }
    __syncthreads();

    // ---- Phase 5: q = y @ Qw2 + Qb2 ----
    if (tid < ADIM) {
        float q = Qb2[tid];
        #pragma unroll 8
        for (int k = 0; k < HID; k++)
            q = fmaf(y_sh[k], Qw2[k * ADIM + tid], q);
        out[(size_t)b * ADIM + tid] = q;
    }
}

extern "C" void kernel_launch(void* const* d_in, const int* in_sizes, int n_in,
                              void* d_out, int out_size) {
    const float* s   = (const float*)d_in[0];
    const float* W1  = (const float*)d_in[1];
    const float* b1  = (const float*)d_in[2];
    const float* W2  = (const float*)d_in[3];
    const float* b2  = (const float*)d_in[4];
    const float* Qw1 = (const float*)d_in[5];
    const float* Qb1 = (const float*)d_in[6];
    const float* Qw2 = (const float*)d_in[7];
    const float* Qb2 = (const float*)d_in[8];
    float* out = (float*)d_out;

    cudaFuncSetAttribute(qnet_kernel,
                         cudaFuncAttributeMaxDynamicSharedMemorySize, SMEM_BYTES);
    qnet_kernel<<<B_TOT, 288, SMEM_BYTES>>>(s, W1, b1, W2, b2,
                                            Qw1, Qb1, Qw2, Qb2, out);
}